// round 6
// baseline (speedup 1.0000x reference)
#include <cuda_runtime.h>
#include <cuda_fp16.h>
#include <cstdint>

// ---------------- problem constants ----------------
#define NN   10000
#define FF   256
#define HH   256
#define CDIM 512                 // 2*HH fused output columns
#define BM   128
#define BN   64
#define BK   32
#define KITERS (FF / BK)         // 8   (single fp16 pass; x and W both rounded to fp16)
#define MTILES ((NN + BM - 1) / BM)  // 79
#define ASTRIDE 40               // smem row stride in halves (80B: 16B-aligned, conflict-free)
#define NSTAGE 4
#define ABYTES (BM * ASTRIDE * 2)   // 10240 per stage
#define BBYTES (BN * ASTRIDE * 2)   // 5120 per stage
#define SMEM_TOTAL (NSTAGE * (ABYTES + BBYTES) + BN * 4)   // 61696
#define EMAX 320000

// ---------------- scratch (allocation-free) ----------------
__device__ __half g_AB [(size_t)NN * CDIM];    // fp16 A|B rows (b1 folded into A half)
__device__ __half g_xh [(size_t)NN * FF];      // x rounded to fp16
__device__ __half g_w  [(size_t)CDIM * FF];    // combined W rows, fp16
__device__ int    g_idx64;
__device__ int    g_hist[NN];                  // per-row edge counts -> bases
__device__ int4   g_sorted[EMAX];              // {r, c, e, 0} sorted by r

// ---------------- PTX helpers ----------------
__device__ __forceinline__ uint32_t smem_u32(const void* p) {
    uint32_t a;
    asm("{ .reg .u64 t; cvta.to.shared.u64 t, %1; cvt.u32.u64 %0, t; }" : "=r"(a) : "l"(p));
    return a;
}
__device__ __forceinline__ void cp_async16(uint32_t dst, const void* src, int src_sz) {
    asm volatile("cp.async.cg.shared.global [%0], [%1], 16, %2;"
                 :: "r"(dst), "l"(src), "r"(src_sz) : "memory");
}
__device__ __forceinline__ void cp_commit() { asm volatile("cp.async.commit_group;" ::: "memory"); }
template <int N>
__device__ __forceinline__ void cp_wait() { asm volatile("cp.async.wait_group %0;" :: "n"(N) : "memory"); }
__device__ __forceinline__ void ldm_x4(uint32_t& r0, uint32_t& r1, uint32_t& r2, uint32_t& r3,
                                       uint32_t addr) {
    asm volatile("ldmatrix.sync.aligned.m8n8.x4.shared.b16 {%0,%1,%2,%3}, [%4];"
                 : "=r"(r0), "=r"(r1), "=r"(r2), "=r"(r3) : "r"(addr));
}

// ---------------- edge index accessor ----------------
__device__ __forceinline__ void load_edge(const long long* ei, int E, int e, int& r, int& c) {
    if (g_idx64) {
        r = (int)ei[e];
        c = (int)ei[(size_t)E + e];
    } else {
        const int* p = (const int*)ei;
        r = p[e];
        c = p[(size_t)E + e];
    }
}

// ---------------- prep: fp16 conversions + hist zero + dtype detect ----------------
#define XQ8 (NN * FF / 8)        // 320000
#define WQ8 (CDIM * FF / 8)      // 16384
#define ZH  (NN / 4)             // 2500 int4 zeroes of g_hist
__global__ void prep_kernel(const float* __restrict__ x, const float* __restrict__ W1,
                            const long long* __restrict__ ei) {
    const int i = blockIdx.x * blockDim.x + threadIdx.x;
    if (i == 0) {
        int ok = 1;
        for (int t = 0; t < 64; t++) {
            long long v = ei[t];
            if (v < 0 || v >= (long long)NN) { ok = 0; break; }
        }
        g_idx64 = ok;
    }
    if (i < XQ8) {
        const int n = i >> 5, k8 = (i & 31) << 3;
        const float* sp = x + ((size_t)n << 8) + k8;
        float4 v0 = *(const float4*)sp;
        float4 v1 = *(const float4*)(sp + 4);
        __half2 h0 = __floats2half2_rn(v0.x, v0.y), h1 = __floats2half2_rn(v0.z, v0.w);
        __half2 h2 = __floats2half2_rn(v1.x, v1.y), h3 = __floats2half2_rn(v1.z, v1.w);
        *(uint4*)(g_xh + ((size_t)n << 8) + k8) =
            make_uint4(*(uint32_t*)&h0, *(uint32_t*)&h1, *(uint32_t*)&h2, *(uint32_t*)&h3);
    } else if (i < XQ8 + WQ8) {
        const int j = i - XQ8;
        const int c = j >> 5, k8 = (j & 31) << 3;
        const float* src = (c < HH) ? (W1 + ((size_t)c << 9) + k8)
                                    : (W1 + ((size_t)(c - HH) << 9) + FF + k8);
        float4 v0 = *(const float4*)src;
        float4 v1 = *(const float4*)(src + 4);
        __half2 h0 = __floats2half2_rn(v0.x, v0.y), h1 = __floats2half2_rn(v0.z, v0.w);
        __half2 h2 = __floats2half2_rn(v1.x, v1.y), h3 = __floats2half2_rn(v1.z, v1.w);
        *(uint4*)(g_w + ((size_t)c << 8) + k8) =
            make_uint4(*(uint32_t*)&h0, *(uint32_t*)&h1, *(uint32_t*)&h2, *(uint32_t*)&h3);
    } else if (i < XQ8 + WQ8 + ZH) {
        ((int4*)g_hist)[i - XQ8 - WQ8] = make_int4(0, 0, 0, 0);
    }
}

// ---------------- sort kernels ----------------
__global__ void hist_kernel(const long long* __restrict__ ei, int E) {
    const int e = blockIdx.x * blockDim.x + threadIdx.x;
    if (e >= E) return;
    int r, c;
    load_edge(ei, E, e, r, c);
    atomicAdd(&g_hist[r], 1);
}

__global__ __launch_bounds__(1024) void scan_kernel() {
    __shared__ int ssum[1024];
    const int t = threadIdx.x;
    const int base = t * 10;                // 1024*10 >= NN
    int local[10], s = 0;
    #pragma unroll
    for (int i = 0; i < 10; i++) {
        int v = (base + i < NN) ? g_hist[base + i] : 0;
        local[i] = s;
        s += v;
    }
    ssum[t] = s;
    __syncthreads();
    #pragma unroll
    for (int off = 1; off < 1024; off <<= 1) {
        int v = (t >= off) ? ssum[t - off] : 0;
        __syncthreads();
        ssum[t] += v;
        __syncthreads();
    }
    const int prev = (t > 0) ? ssum[t - 1] : 0;
    #pragma unroll
    for (int i = 0; i < 10; i++)
        if (base + i < NN) g_hist[base + i] = prev + local[i];
}

__global__ void scatter_kernel(const long long* __restrict__ ei, int E) {
    const int e = blockIdx.x * blockDim.x + threadIdx.x;
    if (e >= E) return;
    int r, c;
    load_edge(ei, E, e, r, c);
    const int pos = atomicAdd(&g_hist[r], 1);
    if (pos < EMAX) g_sorted[pos] = make_int4(r, c, e, 0);
}

// ---------------- phase 1: fp16 mma.sync GEMM, 4-stage pipeline -> g_AB ----------------
__global__ __launch_bounds__(256) void gemm_kernel(const float* __restrict__ b1) {
    extern __shared__ __align__(16) char smem[];
    float* sbias = (float*)(smem + NSTAGE * (ABYTES + BBYTES));

    const int tid = threadIdx.x, lane = tid & 31, wid = tid >> 5;
    const int wm = wid & 3, wn = wid >> 2;            // 4x2 warp grid, 32x32 each
    const int g = lane >> 2, tc = lane & 3;
    const int bm = blockIdx.x * BM;
    const int bn = blockIdx.y * BN;
    const int side = bn >> 8;

    if (tid < BN) sbias[tid] = (side == 0) ? b1[bn + tid] : 0.f;

    const int ar0 = tid >> 2,           aseg = tid & 3;
    const int ar1 = (tid + 256) >> 2;
    const int brow = tid >> 2,          bseg = tid & 3;
    const int arow0_ok = (bm + ar0) < NN ? 16 : 0;
    const int arow1_ok = (bm + ar1) < NN ? 16 : 0;
    const __half* agp0 = g_xh + ((size_t)((bm + ar0) < NN ? (bm + ar0) : 0) << 8) + aseg * 8;
    const __half* agp1 = g_xh + ((size_t)((bm + ar1) < NN ? (bm + ar1) : 0) << 8) + aseg * 8;
    const __half* bgp  = g_w + ((size_t)(bn + brow) << 8) + bseg * 8;

    const uint32_t smem_base = smem_u32(smem);
    uint32_t aS[NSTAGE], bS[NSTAGE];
    #pragma unroll
    for (int s = 0; s < NSTAGE; s++) {
        aS[s] = smem_base + s * ABYTES;
        bS[s] = smem_base + NSTAGE * ABYTES + s * BBYTES;
    }
    const uint32_t adst0 = (uint32_t)(ar0 * ASTRIDE + aseg * 8) * 2;
    const uint32_t adst1 = (uint32_t)(ar1 * ASTRIDE + aseg * 8) * 2;
    const uint32_t bdst  = (uint32_t)(brow * ASTRIDE + bseg * 8) * 2;

    const uint32_t a_loff = (uint32_t)(((wm * 32 + (lane & 15)) * ASTRIDE + (lane >> 4) * 8) * 2);
    const int b_rl = lane & 7, b_q = lane >> 3;
    const uint32_t b_loff = (uint32_t)(((wn * 32 + (b_q >> 1) * 8 + b_rl) * ASTRIDE + (b_q & 1) * 8) * 2);

    float acc[2][4][4];
    #pragma unroll
    for (int mi = 0; mi < 2; mi++)
        #pragma unroll
        for (int ni = 0; ni < 4; ni++)
            #pragma unroll
            for (int q = 0; q < 4; q++) acc[mi][ni][q] = 0.f;

    #pragma unroll
    for (int it = 0; it < NSTAGE - 1; it++) {
        const int k0 = it * BK;
        cp_async16(aS[it] + adst0, agp0 + k0, arow0_ok);
        cp_async16(aS[it] + adst1, agp1 + k0, arow1_ok);
        cp_async16(bS[it] + bdst,  bgp + k0, 16);
        cp_commit();
    }

    for (int it = 0; it < KITERS; it++) {
        cp_wait<NSTAGE - 2>();
        __syncthreads();

        {
            const int nf = it + NSTAGE - 1;
            if (nf < KITERS) {
                const int s = nf & (NSTAGE - 1);
                const int k0 = nf * BK;
                cp_async16(aS[s] + adst0, agp0 + k0, arow0_ok);
                cp_async16(aS[s] + adst1, agp1 + k0, arow1_ok);
                cp_async16(bS[s] + bdst,  bgp + k0, 16);
            }
            cp_commit();
        }

        const int s = it & (NSTAGE - 1);
        const uint32_t As = aS[s] + a_loff;
        const uint32_t Bs = bS[s] + b_loff;

        #pragma unroll
        for (int ks = 0; ks < BK; ks += 16) {
            uint32_t af[2][4], bf[4][2];
            #pragma unroll
            for (int mi = 0; mi < 2; mi++)
                ldm_x4(af[mi][0], af[mi][1], af[mi][2], af[mi][3],
                       As + (uint32_t)((mi * 16 * ASTRIDE + ks) * 2));
            #pragma unroll
            for (int p = 0; p < 2; p++)
                ldm_x4(bf[2 * p][0], bf[2 * p][1], bf[2 * p + 1][0], bf[2 * p + 1][1],
                       Bs + (uint32_t)((p * 16 * ASTRIDE + ks) * 2));
            #pragma unroll
            for (int mi = 0; mi < 2; mi++)
                #pragma unroll
                for (int ni = 0; ni < 4; ni++) {
                    float* c = acc[mi][ni];
                    asm volatile(
                        "mma.sync.aligned.m16n8k16.row.col.f32.f16.f16.f32 "
                        "{%0,%1,%2,%3}, {%4,%5,%6,%7}, {%8,%9}, {%0,%1,%2,%3};"
                        : "+f"(c[0]), "+f"(c[1]), "+f"(c[2]), "+f"(c[3])
                        : "r"(af[mi][0]), "r"(af[mi][1]), "r"(af[mi][2]), "r"(af[mi][3]),
                          "r"(bf[ni][0]), "r"(bf[ni][1]));
                }
        }
    }

    #pragma unroll
    for (int mi = 0; mi < 2; mi++) {
        const int row0 = bm + wm * 32 + mi * 16 + g;
        const int row1 = row0 + 8;
        #pragma unroll
        for (int ni = 0; ni < 4; ni++) {
            const int col = wn * 32 + ni * 8 + tc * 2;
            const float bx = sbias[col], by = sbias[col + 1];
            __half2 h0 = __floats2half2_rn(acc[mi][ni][0] + bx, acc[mi][ni][1] + by);
            __half2 h1 = __floats2half2_rn(acc[mi][ni][2] + bx, acc[mi][ni][3] + by);
            if (row0 < NN) *(__half2*)(g_AB + (size_t)row0 * CDIM + bn + col) = h0;
            if (row1 < NN) *(__half2*)(g_AB + (size_t)row1 * CDIM + bn + col) = h1;
        }
    }
}

// ---------------- phase 2: sorted per-edge fused relu-dot-sigmoid (1 warp / edge) ----------
__global__ __launch_bounds__(512) void edge_kernel(const float* __restrict__ W2,
                                                   const float* __restrict__ b2,
                                                   float* __restrict__ out, int E) {
    const int t = threadIdx.x;
    const int slot = (int)((blockIdx.x * 512u + t) >> 5);
    const int lane = t & 31;
    if (slot >= E) return;

    const int4 s = g_sorted[slot];
    const int r = s.x, c = s.y, e = s.z;

    const uint4 av = *((const uint4*)(g_AB + (size_t)r * CDIM) + lane);        // A cols (b1 folded)
    const uint4 bv = *((const uint4*)(g_AB + (size_t)c * CDIM + HH) + lane);   // B cols
    const float4 w0 = ((const float4*)W2)[lane * 2];
    const float4 w1 = ((const float4*)W2)[lane * 2 + 1];

    const __half2 z2 = __float2half2_rn(0.f);
    __half2 a0 = *(const __half2*)&av.x, a1 = *(const __half2*)&av.y,
            a2 = *(const __half2*)&av.z, a3 = *(const __half2*)&av.w;
    __half2 b0 = *(const __half2*)&bv.x, b1h = *(const __half2*)&bv.y,
            b2h = *(const __half2*)&bv.z, b3 = *(const __half2*)&bv.w;

    __half2 h0 = __hmax2(__hadd2(a0, b0), z2);
    __half2 h1 = __hmax2(__hadd2(a1, b1h), z2);
    __half2 h2 = __hmax2(__hadd2(a2, b2h), z2);
    __half2 h3 = __hmax2(__hadd2(a3, b3), z2);

    float2 f0 = __half22float2(h0), f1 = __half22float2(h1);
    float2 f2 = __half22float2(h2), f3 = __half22float2(h3);

    float acc = 0.f;
    acc = fmaf(f0.x, w0.x, acc); acc = fmaf(f0.y, w0.y, acc);
    acc = fmaf(f1.x, w0.z, acc); acc = fmaf(f1.y, w0.w, acc);
    acc = fmaf(f2.x, w1.x, acc); acc = fmaf(f2.y, w1.y, acc);
    acc = fmaf(f3.x, w1.z, acc); acc = fmaf(f3.y, w1.w, acc);

    #pragma unroll
    for (int o = 16; o > 0; o >>= 1) acc += __shfl_xor_sync(0xFFFFFFFFu, acc, o);

    if (lane == 0) {
        float z = acc + b2[0];                   // TEMPERATURE = 1
        out[e] = 1.f / (1.f + __expf(-z));
    }
}

// ---------------- launch ----------------
extern "C" void kernel_launch(void* const* d_in, const int* in_sizes, int n_in,
                              void* d_out, int out_size) {
    const float*     x   = (const float*)d_in[0];
    const long long* ei  = (const long long*)d_in[1];
    const float*     W1  = (const float*)d_in[2];
    const float*     b1  = (const float*)d_in[3];
    const float*     W2  = (const float*)d_in[4];
    const float*     b2  = (const float*)d_in[5];
    float*           out = (float*)d_out;
    const int E = out_size;   // 320000

    const int ptasks = XQ8 + WQ8 + ZH;
    prep_kernel<<<(ptasks + 255) / 256, 256>>>(x, W1, ei);       // also zeroes hist, sets idx64

    hist_kernel<<<(E + 255) / 256, 256>>>(ei, E);
    scan_kernel<<<1, 1024>>>();
    scatter_kernel<<<(E + 255) / 256, 256>>>(ei, E);

    cudaFuncSetAttribute(gemm_kernel, cudaFuncAttributeMaxDynamicSharedMemorySize, SMEM_TOTAL);
    dim3 ggrid(MTILES, CDIM / BN);                                // (79, 8)
    gemm_kernel<<<ggrid, 256, SMEM_TOTAL>>>(b1);

    int eblocks = (E + 15) / 16;                                  // 16 warps/block, 1 warp/edge
    edge_kernel<<<eblocks, 512>>>(W2, b2, out, E);
}

// round 7
// speedup vs baseline: 1.4250x; 1.4250x over previous
#include <cuda_runtime.h>
#include <cuda_fp16.h>
#include <cstdint>

// ---------------- problem constants ----------------
#define NN   10000
#define FF   256
#define HH   256
#define CDIM 512                 // 2*HH fused output columns
#define BM   128
#define BN   64
#define BK   32
#define KITERS (FF / BK)         // 8  (single fp16 pass; x and W both rounded to fp16)
#define MTILES ((NN + BM - 1) / BM)  // 79
#define ASTRIDE 40               // smem row stride in halves (80B: 16B-aligned, conflict-free)
#define NSTAGE 4
#define ABYTES (BM * ASTRIDE * 2)   // 10240 per stage
#define BBYTES (BN * ASTRIDE * 2)   // 5120 per stage
#define SMEM_TOTAL (NSTAGE * (ABYTES + BBYTES) + BN * 4)   // 61696

// ---------------- scratch (allocation-free) ----------------
__device__ __half g_AB [(size_t)NN * CDIM];    // fp16 A|B rows (b1 folded into A half)
__device__ __half g_xh [(size_t)NN * FF];      // x rounded to fp16
__device__ __half g_w  [(size_t)CDIM * FF];    // combined W rows, fp16
__device__ int    g_idx64;

// ---------------- PTX helpers ----------------
__device__ __forceinline__ uint32_t smem_u32(const void* p) {
    uint32_t a;
    asm("{ .reg .u64 t; cvta.to.shared.u64 t, %1; cvt.u32.u64 %0, t; }" : "=r"(a) : "l"(p));
    return a;
}
__device__ __forceinline__ void cp_async16(uint32_t dst, const void* src, int src_sz) {
    asm volatile("cp.async.cg.shared.global [%0], [%1], 16, %2;"
                 :: "r"(dst), "l"(src), "r"(src_sz) : "memory");
}
__device__ __forceinline__ void cp_commit() { asm volatile("cp.async.commit_group;" ::: "memory"); }
template <int N>
__device__ __forceinline__ void cp_wait() { asm volatile("cp.async.wait_group %0;" :: "n"(N) : "memory"); }
__device__ __forceinline__ void ldm_x4(uint32_t& r0, uint32_t& r1, uint32_t& r2, uint32_t& r3,
                                       uint32_t addr) {
    asm volatile("ldmatrix.sync.aligned.m8n8.x4.shared.b16 {%0,%1,%2,%3}, [%4];"
                 : "=r"(r0), "=r"(r1), "=r"(r2), "=r"(r3) : "r"(addr));
}

// ---------------- prep: fp16 conversions + dtype detect (8 floats / thread) ------------
#define XQ8 (NN * FF / 8)        // 320000
#define WQ8 (CDIM * FF / 8)      // 16384
__global__ void prep_kernel(const float* __restrict__ x, const float* __restrict__ W1,
                            const long long* __restrict__ ei) {
    const int i = blockIdx.x * blockDim.x + threadIdx.x;
    if (i == 0) {
        int ok = 1;
        for (int t = 0; t < 64; t++) {
            long long v = ei[t];
            if (v < 0 || v >= (long long)NN) { ok = 0; break; }
        }
        g_idx64 = ok;
    }
    if (i < XQ8) {
        const int n = i >> 5, k8 = (i & 31) << 3;
        const float* sp = x + ((size_t)n << 8) + k8;
        float4 v0 = *(const float4*)sp;
        float4 v1 = *(const float4*)(sp + 4);
        __half2 h0 = __floats2half2_rn(v0.x, v0.y), h1 = __floats2half2_rn(v0.z, v0.w);
        __half2 h2 = __floats2half2_rn(v1.x, v1.y), h3 = __floats2half2_rn(v1.z, v1.w);
        *(uint4*)(g_xh + ((size_t)n << 8) + k8) =
            make_uint4(*(uint32_t*)&h0, *(uint32_t*)&h1, *(uint32_t*)&h2, *(uint32_t*)&h3);
    } else if (i < XQ8 + WQ8) {
        const int j = i - XQ8;
        const int c = j >> 5, k8 = (j & 31) << 3;
        const float* src = (c < HH) ? (W1 + ((size_t)c << 9) + k8)
                                    : (W1 + ((size_t)(c - HH) << 9) + FF + k8);
        float4 v0 = *(const float4*)src;
        float4 v1 = *(const float4*)(src + 4);
        __half2 h0 = __floats2half2_rn(v0.x, v0.y), h1 = __floats2half2_rn(v0.z, v0.w);
        __half2 h2 = __floats2half2_rn(v1.x, v1.y), h3 = __floats2half2_rn(v1.z, v1.w);
        *(uint4*)(g_w + ((size_t)c << 8) + k8) =
            make_uint4(*(uint32_t*)&h0, *(uint32_t*)&h1, *(uint32_t*)&h2, *(uint32_t*)&h3);
    }
}

// ---------------- phase 1: fp16 mma.sync GEMM (K=256), 4-stage pipeline -> g_AB ----------
__global__ __launch_bounds__(256) void gemm_kernel(const float* __restrict__ b1) {
    extern __shared__ __align__(16) char smem[];
    float* sbias = (float*)(smem + NSTAGE * (ABYTES + BBYTES));

    const int tid = threadIdx.x, lane = tid & 31, wid = tid >> 5;
    const int wm = wid & 3, wn = wid >> 2;            // 4x2 warp grid, 32x32 each
    const int g = lane >> 2, tc = lane & 3;
    const int bm = blockIdx.x * BM;
    const int bn = blockIdx.y * BN;
    const int side = bn >> 8;

    if (tid < BN) sbias[tid] = (side == 0) ? b1[bn + tid] : 0.f;

    const int ar0 = tid >> 2,           aseg = tid & 3;
    const int ar1 = (tid + 256) >> 2;
    const int brow = tid >> 2,          bseg = tid & 3;
    const int arow0_ok = (bm + ar0) < NN ? 16 : 0;
    const int arow1_ok = (bm + ar1) < NN ? 16 : 0;
    const __half* agp0 = g_xh + ((size_t)((bm + ar0) < NN ? (bm + ar0) : 0) << 8) + aseg * 8;
    const __half* agp1 = g_xh + ((size_t)((bm + ar1) < NN ? (bm + ar1) : 0) << 8) + aseg * 8;
    const __half* bgp  = g_w + ((size_t)(bn + brow) << 8) + bseg * 8;

    const uint32_t smem_base = smem_u32(smem);
    uint32_t aS[NSTAGE], bS[NSTAGE];
    #pragma unroll
    for (int s = 0; s < NSTAGE; s++) {
        aS[s] = smem_base + s * ABYTES;
        bS[s] = smem_base + NSTAGE * ABYTES + s * BBYTES;
    }
    const uint32_t adst0 = (uint32_t)(ar0 * ASTRIDE + aseg * 8) * 2;
    const uint32_t adst1 = (uint32_t)(ar1 * ASTRIDE + aseg * 8) * 2;
    const uint32_t bdst  = (uint32_t)(brow * ASTRIDE + bseg * 8) * 2;

    const uint32_t a_loff = (uint32_t)(((wm * 32 + (lane & 15)) * ASTRIDE + (lane >> 4) * 8) * 2);
    const int b_rl = lane & 7, b_q = lane >> 3;
    const uint32_t b_loff = (uint32_t)(((wn * 32 + (b_q >> 1) * 8 + b_rl) * ASTRIDE + (b_q & 1) * 8) * 2);

    float acc[2][4][4];
    #pragma unroll
    for (int mi = 0; mi < 2; mi++)
        #pragma unroll
        for (int ni = 0; ni < 4; ni++)
            #pragma unroll
            for (int q = 0; q < 4; q++) acc[mi][ni][q] = 0.f;

    #pragma unroll
    for (int it = 0; it < NSTAGE - 1; it++) {
        const int k0 = it * BK;
        cp_async16(aS[it] + adst0, agp0 + k0, arow0_ok);
        cp_async16(aS[it] + adst1, agp1 + k0, arow1_ok);
        cp_async16(bS[it] + bdst,  bgp + k0, 16);
        cp_commit();
    }

    for (int it = 0; it < KITERS; it++) {
        cp_wait<NSTAGE - 2>();
        __syncthreads();

        {
            const int nf = it + NSTAGE - 1;
            if (nf < KITERS) {
                const int s = nf & (NSTAGE - 1);
                const int k0 = nf * BK;
                cp_async16(aS[s] + adst0, agp0 + k0, arow0_ok);
                cp_async16(aS[s] + adst1, agp1 + k0, arow1_ok);
                cp_async16(bS[s] + bdst,  bgp + k0, 16);
            }
            cp_commit();
        }

        const int s = it & (NSTAGE - 1);
        const uint32_t As = aS[s] + a_loff;
        const uint32_t Bs = bS[s] + b_loff;

        #pragma unroll
        for (int ks = 0; ks < BK; ks += 16) {
            uint32_t af[2][4], bf[4][2];
            #pragma unroll
            for (int mi = 0; mi < 2; mi++)
                ldm_x4(af[mi][0], af[mi][1], af[mi][2], af[mi][3],
                       As + (uint32_t)((mi * 16 * ASTRIDE + ks) * 2));
            #pragma unroll
            for (int p = 0; p < 2; p++)
                ldm_x4(bf[2 * p][0], bf[2 * p][1], bf[2 * p + 1][0], bf[2 * p + 1][1],
                       Bs + (uint32_t)((p * 16 * ASTRIDE + ks) * 2));
            #pragma unroll
            for (int mi = 0; mi < 2; mi++)
                #pragma unroll
                for (int ni = 0; ni < 4; ni++) {
                    float* c = acc[mi][ni];
                    asm volatile(
                        "mma.sync.aligned.m16n8k16.row.col.f32.f16.f16.f32 "
                        "{%0,%1,%2,%3}, {%4,%5,%6,%7}, {%8,%9}, {%0,%1,%2,%3};"
                        : "+f"(c[0]), "+f"(c[1]), "+f"(c[2]), "+f"(c[3])
                        : "r"(af[mi][0]), "r"(af[mi][1]), "r"(af[mi][2]), "r"(af[mi][3]),
                          "r"(bf[ni][0]), "r"(bf[ni][1]));
                }
        }
    }

    #pragma unroll
    for (int mi = 0; mi < 2; mi++) {
        const int row0 = bm + wm * 32 + mi * 16 + g;
        const int row1 = row0 + 8;
        #pragma unroll
        for (int ni = 0; ni < 4; ni++) {
            const int col = wn * 32 + ni * 8 + tc * 2;
            const float bx = sbias[col], by = sbias[col + 1];
            __half2 h0 = __floats2half2_rn(acc[mi][ni][0] + bx, acc[mi][ni][1] + by);
            __half2 h1 = __floats2half2_rn(acc[mi][ni][2] + bx, acc[mi][ni][3] + by);
            if (row0 < NN) *(__half2*)(g_AB + (size_t)row0 * CDIM + bn + col) = h0;
            if (row1 < NN) *(__half2*)(g_AB + (size_t)row1 * CDIM + bn + col) = h1;
        }
    }
}

// ---------------- phase 2: per-edge fused relu-dot-sigmoid (1 warp / edge, fp16 AB) --------
__global__ __launch_bounds__(256) void edge_kernel(const long long* __restrict__ ei,
                                                   const float* __restrict__ W2,
                                                   const float* __restrict__ b2,
                                                   float* __restrict__ out, int E) {
    const int t = threadIdx.x;
    const int e = (int)((blockIdx.x * 256u + t) >> 5);
    const int lane = t & 31;
    if (e >= E) return;

    long long r, c;
    if (g_idx64) {
        r = ei[e];
        c = ei[(size_t)E + e];
    } else {
        const int* p = (const int*)ei;
        r = p[e];
        c = p[(size_t)E + e];
    }

    const uint4 av = *((const uint4*)(g_AB + (size_t)r * CDIM) + lane);        // A cols (b1 folded)
    const uint4 bv = *((const uint4*)(g_AB + (size_t)c * CDIM + HH) + lane);   // B cols
    const float4 w0 = ((const float4*)W2)[lane * 2];
    const float4 w1 = ((const float4*)W2)[lane * 2 + 1];

    const __half2 z2 = __float2half2_rn(0.f);
    __half2 a0 = *(const __half2*)&av.x, a1 = *(const __half2*)&av.y,
            a2 = *(const __half2*)&av.z, a3 = *(const __half2*)&av.w;
    __half2 b0 = *(const __half2*)&bv.x, b1h = *(const __half2*)&bv.y,
            b2h = *(const __half2*)&bv.z, b3 = *(const __half2*)&bv.w;

    __half2 h0 = __hmax2(__hadd2(a0, b0), z2);
    __half2 h1 = __hmax2(__hadd2(a1, b1h), z2);
    __half2 h2 = __hmax2(__hadd2(a2, b2h), z2);
    __half2 h3 = __hmax2(__hadd2(a3, b3), z2);

    float2 f0 = __half22float2(h0), f1 = __half22float2(h1);
    float2 f2 = __half22float2(h2), f3 = __half22float2(h3);

    float acc = 0.f;
    acc = fmaf(f0.x, w0.x, acc); acc = fmaf(f0.y, w0.y, acc);
    acc = fmaf(f1.x, w0.z, acc); acc = fmaf(f1.y, w0.w, acc);
    acc = fmaf(f2.x, w1.x, acc); acc = fmaf(f2.y, w1.y, acc);
    acc = fmaf(f3.x, w1.z, acc); acc = fmaf(f3.y, w1.w, acc);

    #pragma unroll
    for (int o = 16; o > 0; o >>= 1) acc += __shfl_xor_sync(0xFFFFFFFFu, acc, o);

    if (lane == 0) {
        float z = acc + b2[0];                   // TEMPERATURE = 1
        out[e] = 1.f / (1.f + __expf(-z));
    }
}

// ---------------- launch ----------------
extern "C" void kernel_launch(void* const* d_in, const int* in_sizes, int n_in,
                              void* d_out, int out_size) {
    const float*     x   = (const float*)d_in[0];
    const long long* ei  = (const long long*)d_in[1];
    const float*     W1  = (const float*)d_in[2];
    const float*     b1  = (const float*)d_in[3];
    const float*     W2  = (const float*)d_in[4];
    const float*     b2  = (const float*)d_in[5];
    float*           out = (float*)d_out;
    const int E = out_size;   // 320000

    const int ptasks = XQ8 + WQ8;                    // 336384
    prep_kernel<<<(ptasks + 255) / 256, 256>>>(x, W1, ei);

    cudaFuncSetAttribute(gemm_kernel, cudaFuncAttributeMaxDynamicSharedMemorySize, SMEM_TOTAL);
    dim3 ggrid(MTILES, CDIM / BN);                   // (79, 8)
    gemm_kernel<<<ggrid, 256, SMEM_TOTAL>>>(b1);

    int eblocks = (E + 7) / 8;                       // 1 warp/edge
    edge_kernel<<<eblocks, 256>>>(ei, W2, b2, out, E);
}